// round 9
// baseline (speedup 1.0000x reference)
#include <cuda_runtime.h>
#include <math.h>

// Problem constants
#define BB 8
#define NN 128
#define HN_ 256
#define HE_ 128
#define NH 8
#define DH_ 32
#define PP 8128
#define BP 65024   // B * P

typedef unsigned long long ull;

__device__ __forceinline__ ull pk2(float x, float y) {
    ull r; asm("mov.b64 %0,{%1,%2};" : "=l"(r) : "f"(x), "f"(y)); return r;
}
__device__ __forceinline__ float2 upk2(ull v) {
    float2 f; asm("mov.b64 {%0,%1},%2;" : "=f"(f.x), "=f"(f.y) : "l"(v)); return f;
}
// d = a*b + d  (packed f32x2 FFMA — PTX-only path, 2 FMAs per issue slot)
__device__ __forceinline__ void fma2(ull& d, ull a, ull b) {
    asm("fma.rn.f32x2 %0,%1,%2,%0;" : "+l"(d) : "l"(a), "l"(b));
}

// Scratch (no cudaMalloc allowed -> __device__ globals)
__device__ float g_n_in[1024 * 256];     // [B*N, HN]
__device__ float g_qkv[1024 * 768];      // [B*N, 3*HN]
__device__ float g_e_in[BP * 128];       // [B*P, HE]
__device__ float g_att[64 * 128 * 128];  // [B*H, N, N] adj -> probs (in place)
__device__ float g_aggE[1024 * 8 * 128]; // [B*N, H, HE]
__device__ float g_anyv[1024];           // [B*N]
__device__ float g_attn[1024 * 256];     // [B*N, HN]
__device__ float g_comb[1024 * 256];     // [B*N, HN]

__device__ __forceinline__ int pair_idx(int i, int j) {
    if (i > j) { int t = i; i = j; j = t; }
    return i * (255 - i) / 2 + (j - i - 1);
}

// ---------------------------------------------------------------------------
// K1: node LayerNorm.  grid = 1024, block = 256
// ---------------------------------------------------------------------------
__global__ void k_node_ln(const float* __restrict__ nf,
                          const float* __restrict__ gn,
                          const float* __restrict__ bn) {
    int row = blockIdx.x;
    int t = threadIdx.x;
    float x = nf[row * 256 + t];
    float s = x, s2 = x * x;
    #pragma unroll
    for (int o = 16; o; o >>= 1) {
        s  += __shfl_xor_sync(0xFFFFFFFFu, s,  o);
        s2 += __shfl_xor_sync(0xFFFFFFFFu, s2, o);
    }
    __shared__ float rs_[8], rs2_[8];
    int w = t >> 5, l = t & 31;
    if (l == 0) { rs_[w] = s; rs2_[w] = s2; }
    __syncthreads();
    float tot = 0.f, tot2 = 0.f;
    #pragma unroll
    for (int i = 0; i < 8; i++) { tot += rs_[i]; tot2 += rs2_[i]; }
    float mean = tot * (1.0f / 256.0f);
    float var  = tot2 * (1.0f / 256.0f) - mean * mean;
    float rstd = rsqrtf(var + 1e-5f);
    g_n_in[row * 256 + t] = (x - mean) * rstd * gn[t] + bn[t];
}

// ---------------------------------------------------------------------------
// K2: qkv GEMM. n_in[1024,256] @ Wqkv[256,768]. grid=(64,3), block=256.
// fma2 packed accumulators.
// ---------------------------------------------------------------------------
__global__ void k_qkv(const float* __restrict__ W, const float* __restrict__ bias) {
    __shared__ float As[16 * 256];
    int t = threadIdx.x;
    int row0 = blockIdx.x * 16;
    int cb = blockIdx.y * 256;
    const float4* a4 = (const float4*)(g_n_in + row0 * 256);
    float4* s4 = (float4*)As;
    #pragma unroll
    for (int i = t; i < 1024; i += 256) s4[i] = a4[i];
    __syncthreads();
    int cg = t & 63;
    int rg = t >> 6;
    ull acc[4][2];
    #pragma unroll
    for (int r = 0; r < 4; r++) { acc[r][0] = 0ULL; acc[r][1] = 0ULL; }
    #pragma unroll 4
    for (int k = 0; k < 256; k++) {
        ulonglong2 wv = *(const ulonglong2*)&W[k * 768 + cb + cg * 4];
        #pragma unroll
        for (int r = 0; r < 4; r++) {
            float a = As[(rg * 4 + r) * 256 + k];
            ull ap = pk2(a, a);
            fma2(acc[r][0], ap, wv.x);
            fma2(acc[r][1], ap, wv.y);
        }
    }
    float4 bb = *(const float4*)&bias[cb + cg * 4];
    #pragma unroll
    for (int r = 0; r < 4; r++) {
        float2 a01 = upk2(acc[r][0]), a23 = upk2(acc[r][1]);
        float4 o;
        o.x = a01.x + bb.x; o.y = a01.y + bb.y;
        o.z = a23.x + bb.z; o.w = a23.y + bb.w;
        *(float4*)&g_qkv[(row0 + rg * 4 + r) * 768 + cb + cg * 4] = o;
    }
}

// ---------------------------------------------------------------------------
// K3: edge LayerNorm + e_adj scatter into g_att (mask & bias folded in).
// grid = 1016 (64 edge rows per block), block = 256.  es padded to 132/row.
// ---------------------------------------------------------------------------
__global__ void k_edge(const float* __restrict__ ef,
                       const float* __restrict__ ge, const float* __restrict__ be,
                       const float* __restrict__ Wea, const float* __restrict__ bea,
                       const int* __restrict__ i1, const int* __restrict__ i2,
                       const float* __restrict__ mask) {
    __shared__ float es[64 * 132];
    __shared__ float wa[128 * 8];
    __shared__ float ges[128], bes[128];
    __shared__ int s_i[64], s_j[64];
    __shared__ float s_mask[64];
    int t = threadIdx.x;
    int base_row = blockIdx.x * 64;
    int b = base_row / 8128;
    int p0 = base_row - b * 8128;
    int base = base_row * 128;

    float4* es4 = (float4*)es;
    const float4* ef4 = (const float4*)(ef + base);
    #pragma unroll
    for (int i = t; i < 2048; i += 256) es4[(i >> 5) * 33 + (i & 31)] = ef4[i];
    for (int i = t; i < 1024; i += 256) wa[i] = Wea[i];
    if (t < 128) { ges[t] = ge[t]; bes[t] = be[t]; }
    if (t < 64) {
        int p = p0 + t;
        s_i[t] = i1[p]; s_j[t] = i2[p];
        s_mask[t] = mask[b * PP + p];
    }
    __syncthreads();

    int w = t >> 5, l = t & 31;
    #pragma unroll
    for (int rr = 0; rr < 8; rr++) {
        int r = w * 8 + rr;
        float4 v = *(float4*)&es[r * 132 + l * 4];
        float s  = v.x + v.y + v.z + v.w;
        float s2 = v.x * v.x + v.y * v.y + v.z * v.z + v.w * v.w;
        #pragma unroll
        for (int o = 16; o; o >>= 1) {
            s  += __shfl_xor_sync(0xFFFFFFFFu, s,  o);
            s2 += __shfl_xor_sync(0xFFFFFFFFu, s2, o);
        }
        float mean = s * (1.0f / 128.0f);
        float var  = s2 * (1.0f / 128.0f) - mean * mean;
        float rstd = rsqrtf(var + 1e-5f);
        int c = l * 4;
        float4 o4;
        o4.x = (v.x - mean) * rstd * ges[c + 0] + bes[c + 0];
        o4.y = (v.y - mean) * rstd * ges[c + 1] + bes[c + 1];
        o4.z = (v.z - mean) * rstd * ges[c + 2] + bes[c + 2];
        o4.w = (v.w - mean) * rstd * ges[c + 3] + bes[c + 3];
        *(float4*)&es[r * 132 + c] = o4;
    }
    __syncthreads();

    float4* out4 = (float4*)(g_e_in + base);
    #pragma unroll
    for (int i = t; i < 2048; i += 256) out4[i] = es4[(i >> 5) * 33 + (i & 31)];

    // e_adj: thread = (row r, head pair q) -> 2 heads, float4 es reads
    {
        int r = t >> 2, q = t & 3;
        float s0 = 0.f, s1 = 0.f;
        #pragma unroll 8
        for (int c4 = 0; c4 < 32; c4++) {
            float4 e4 = *(float4*)&es[r * 132 + c4 * 4];
            int c = c4 * 4;
            float2 w0 = *(float2*)&wa[(c + 0) * 8 + q * 2];
            float2 w1 = *(float2*)&wa[(c + 1) * 8 + q * 2];
            float2 w2 = *(float2*)&wa[(c + 2) * 8 + q * 2];
            float2 w3 = *(float2*)&wa[(c + 3) * 8 + q * 2];
            s0 += e4.x * w0.x + e4.y * w1.x + e4.z * w2.x + e4.w * w3.x;
            s1 += e4.x * w0.y + e4.y * w1.y + e4.z * w2.y + e4.w * w3.y;
        }
        float m = s_mask[r];
        float v0 = (m == 0.f) ? -1e20f : (s0 + bea[q * 2]);
        float v1 = (m == 0.f) ? -1e20f : (s1 + bea[q * 2 + 1]);
        int ni = s_i[r], nj = s_j[r];
        float* Ab0 = g_att + (size_t)(b * 8 + q * 2) * 16384;
        float* Ab1 = Ab0 + 16384;
        Ab0[ni * 128 + nj] = v0;
        Ab0[nj * 128 + ni] = v0;
        Ab1[ni * 128 + nj] = v1;
        Ab1[nj * 128 + ni] = v1;
    }
}

// ---------------------------------------------------------------------------
// K4: fused logits + softmax + P@V.
// grid = 256 (b, h, n-quarter of 32 rows), block = 256.
// K tile stored transposed [k][m] (pad 132) -> conflict-free LDS.128 kv loads.
// Logits via packed fma2.
// ---------------------------------------------------------------------------
__global__ void k_lsm() {
    int bx = blockIdx.x;
    int b = bx >> 5, h = (bx >> 2) & 7, nq = bx & 3;
    int n0 = nq * 32;
    __shared__ float Qs[32 * 36];
    __shared__ float KV[128 * 36];   // first used as Ks_t[k*132+m], then Vs[m*36+d]
    __shared__ float Ps[32 * 132];
    int t = threadIdx.x;

    {   // Q rows n0..n0+31 : exactly one float4 per thread
        int n = t >> 3, f = t & 7;
        float4 q = *(const float4*)&g_qkv[(size_t)(b * 128 + n0 + n) * 768 + h * 32 + f * 4];
        *(float4*)&Qs[n * 36 + f * 4] = q;
    }
    #pragma unroll
    for (int i = t; i < 1024; i += 256) {   // K transposed store
        int m = i >> 3, f = i & 7;
        float4 kk = *(const float4*)&g_qkv[(size_t)(b * 128 + m) * 768 + 256 + h * 32 + f * 4];
        KV[(f * 4 + 0) * 132 + m] = kk.x;
        KV[(f * 4 + 1) * 132 + m] = kk.y;
        KV[(f * 4 + 2) * 132 + m] = kk.z;
        KV[(f * 4 + 3) * 132 + m] = kk.w;
    }
    __syncthreads();

    int n_g = t >> 5;   // warp id = query-row group (4 rows)
    int m_g = t & 31;   // lane = key group (4 keys)
    ull acc2[4][2];
    #pragma unroll
    for (int i = 0; i < 4; i++) { acc2[i][0] = 0ULL; acc2[i][1] = 0ULL; }

    #pragma unroll 8
    for (int k = 0; k < 32; k++) {
        ulonglong2 kv = *(const ulonglong2*)&KV[k * 132 + m_g * 4];
        #pragma unroll
        for (int i = 0; i < 4; i++) {
            float q = Qs[(n_g * 4 + i) * 36 + k];
            ull qp = pk2(q, q);
            fma2(acc2[i][0], qp, kv.x);
            fma2(acc2[i][1], qp, kv.y);
        }
    }

    const float scale = 0.17677669529663687f;  // 1/sqrt(32)
    float* Lb = g_att + (size_t)(b * 8 + h) * 16384;
    #pragma unroll
    for (int i = 0; i < 4; i++) {
        int n = n0 + n_g * 4 + i;
        float2 a01 = upk2(acc2[i][0]), a23 = upk2(acc2[i][1]);
        float4 adj = *(const float4*)&Lb[n * 128 + m_g * 4];
        float lg[4];
        lg[0] = (n == m_g * 4 + 0) ? -1e20f : fmaf(a01.x, scale, adj.x);
        lg[1] = (n == m_g * 4 + 1) ? -1e20f : fmaf(a01.y, scale, adj.y);
        lg[2] = (n == m_g * 4 + 2) ? -1e20f : fmaf(a23.x, scale, adj.z);
        lg[3] = (n == m_g * 4 + 3) ? -1e20f : fmaf(a23.y, scale, adj.w);
        float mx = fmaxf(fmaxf(lg[0], lg[1]), fmaxf(lg[2], lg[3]));
        #pragma unroll
        for (int o = 16; o; o >>= 1) mx = fmaxf(mx, __shfl_xor_sync(0xFFFFFFFFu, mx, o));
        float anyv = (mx > -1e19f) ? 1.f : 0.f;
        float e0 = __expf(lg[0] - mx), e1 = __expf(lg[1] - mx);
        float e2 = __expf(lg[2] - mx), e3 = __expf(lg[3] - mx);
        float sum = e0 + e1 + e2 + e3;
        #pragma unroll
        for (int o = 16; o; o >>= 1) sum += __shfl_xor_sync(0xFFFFFFFFu, sum, o);
        float inv = anyv / sum;
        float4 p = make_float4(e0 * inv, e1 * inv, e2 * inv, e3 * inv);
        *(float4*)&Ps[(n_g * 4 + i) * 132 + m_g * 4] = p;
        *(float4*)&Lb[n * 128 + m_g * 4] = p;
        if (m_g == 0) g_anyv[b * 128 + n] = anyv;   // identical across h: benign
    }
    __syncthreads();

    // stage V into KV (natural layout [m][36])
    #pragma unroll
    for (int i = t; i < 1024; i += 256) {
        int m = i >> 3, f = i & 7;
        float4 v = *(const float4*)&g_qkv[(size_t)(b * 128 + m) * 768 + 512 + h * 32 + f * 4];
        *(float4*)&KV[m * 36 + f * 4] = v;
    }
    __syncthreads();

    // P @ V : thread = (row group ng2, dim d); 4 rows each
    {
        int d = t & 31, ng2 = t >> 5;
        float a2[4];
        #pragma unroll
        for (int j = 0; j < 4; j++) a2[j] = 0.f;
        #pragma unroll 4
        for (int m = 0; m < 128; m++) {
            float v = KV[m * 36 + d];
            #pragma unroll
            for (int j = 0; j < 4; j++) a2[j] += Ps[(ng2 + 8 * j) * 132 + m] * v;
        }
        #pragma unroll
        for (int j = 0; j < 4; j++) {
            int n = n0 + ng2 + 8 * j;
            g_attn[(size_t)(b * 128 + n) * 256 + h * 32 + d] = a2[j];
        }
    }
}

// ---------------------------------------------------------------------------
// K5: e_in aggregation over neighbors (probs read from g_att).
// grid = 1024 (one (b,n)), block = 256.
// Thread = (col-float4 cg, 8-way m-split ms): each ev float4 feeds ALL 8 heads.
// ---------------------------------------------------------------------------
__global__ void k_agg() {
    int bx = blockIdx.x;
    int b = bx >> 7, n = bx & 127;
    int t = threadIdx.x;
    int cg = t & 31, ms = t >> 5;

    __shared__ float ps[8 * 128];
    __shared__ int pidx_s[128];
    __shared__ float psum[64 * 128];   // [ms*8+h][128]

    if (t < 128) pidx_s[t] = (t == n) ? 0 : pair_idx(n, t);
    {   // load probs: 8 heads x 128, one float4 per thread
        int hh = t >> 5, mg = t & 31;
        const float* Lb = g_att + ((size_t)(b * 8 + hh) * 128 + n) * 128;
        *(float4*)&ps[hh * 128 + mg * 4] = *(const float4*)&Lb[mg * 4];
    }
    __syncthreads();

    int pbase = b * PP;
    ull acc[8][2];
    #pragma unroll
    for (int hh = 0; hh < 8; hh++) { acc[hh][0] = 0ULL; acc[hh][1] = 0ULL; }

    int mbeg = ms * 16;
    #pragma unroll 2
    for (int mm = 0; mm < 16; mm++) {
        int m = mbeg + mm;
        ulonglong2 ev = *(const ulonglong2*)&g_e_in[(size_t)(pbase + pidx_s[m]) * 128 + cg * 4];
        #pragma unroll
        for (int hh = 0; hh < 8; hh++) {
            float pr = ps[hh * 128 + m];
            ull pp = pk2(pr, pr);
            fma2(acc[hh][0], pp, ev.x);
            fma2(acc[hh][1], pp, ev.y);
        }
    }
    #pragma unroll
    for (int hh = 0; hh < 8; hh++) {
        ulonglong2 v; v.x = acc[hh][0]; v.y = acc[hh][1];
        *(ulonglong2*)&psum[(ms * 8 + hh) * 128 + cg * 4] = v;
    }
    __syncthreads();

    // reduce the 8 m-splits
    int hh = t >> 5, cc = t & 31;
    float4 o = make_float4(0.f, 0.f, 0.f, 0.f);
    #pragma unroll
    for (int s = 0; s < 8; s++) {
        float4 r = *(float4*)&psum[(s * 8 + hh) * 128 + cc * 4];
        o.x += r.x; o.y += r.y; o.z += r.z; o.w += r.w;
    }
    *(float4*)&g_aggE[(size_t)bx * 1024 + hh * 128 + cc * 4] = o;
}

// ---------------------------------------------------------------------------
// K6: g_attn += aggE @ Wev + anyv * bev.  grid = 256 (4 rows), block = 256.
// Thread = (col-float4 cg, row rg); float4 weight loads + fma2.
// ---------------------------------------------------------------------------
__global__ void k_proj(const float* __restrict__ Wev, const float* __restrict__ bev) {
    __shared__ float aE[4 * 1024];
    int t = threadIdx.x;
    int row0 = blockIdx.x * 4;
    const float4* src = (const float4*)(g_aggE + (size_t)row0 * 1024);
    float4* dst = (float4*)aE;
    #pragma unroll
    for (int i = t; i < 1024; i += 256) dst[i] = src[i];
    __syncthreads();

    int cg = t & 63;     // cols cg*4 (head h = cg>>3, cols stay inside one head)
    int rg = t >> 6;     // one row
    int h = cg >> 3;
    ull acc0 = 0ULL, acc1 = 0ULL;
    #pragma unroll 4
    for (int c = 0; c < 128; c++) {
        ulonglong2 wv = *(const ulonglong2*)&Wev[c * 256 + cg * 4];
        float a = aE[rg * 1024 + h * 128 + c];
        ull ap = pk2(a, a);
        fma2(acc0, ap, wv.x);
        fma2(acc1, ap, wv.y);
    }
    float4 bb = *(const float4*)&bev[cg * 4];
    int bn = row0 + rg;
    float any = g_anyv[bn];
    float2 a01 = upk2(acc0), a23 = upk2(acc1);
    float4 cur = *(float4*)&g_attn[(size_t)bn * 256 + cg * 4];
    float4 o;
    o.x = cur.x + a01.x + any * bb.x;
    o.y = cur.y + a01.y + any * bb.y;
    o.z = cur.z + a23.x + any * bb.z;
    o.w = cur.w + a23.y + any * bb.w;
    *(float4*)&g_attn[(size_t)bn * 256 + cg * 4] = o;
}

// ---------------------------------------------------------------------------
// K7a: comb = gelu(cat(n_in,attn)@Wo+bo).  grid = (128 rowtiles, 2 colhalves),
// block = 256.  8 rows/block, 128 cols/block -> halved Wo L2 traffic.
// ---------------------------------------------------------------------------
__global__ void k_out1(const float* __restrict__ Wo, const float* __restrict__ bo) {
    __shared__ float cs[8 * 512];
    int row0 = blockIdx.x * 8;
    int cb = blockIdx.y * 128;
    int t = threadIdx.x;
    #pragma unroll
    for (int i = t; i < 1024; i += 256) {
        int r = i >> 7, f = i & 127;
        float4 v = (f < 64)
            ? *(const float4*)&g_n_in[(size_t)(row0 + r) * 256 + f * 4]
            : *(const float4*)&g_attn[(size_t)(row0 + r) * 256 + (f - 64) * 4];
        *(float4*)&cs[r * 512 + f * 4] = v;
    }
    __syncthreads();

    int cg = t & 31;   // cols cb + cg*4
    int rg = t >> 5;   // one row
    ull acc0 = 0ULL, acc1 = 0ULL;
    #pragma unroll 4
    for (int k = 0; k < 512; k++) {
        ulonglong2 wv = *(const ulonglong2*)&Wo[k * 256 + cb + cg * 4];
        float a = cs[rg * 512 + k];
        ull ap = pk2(a, a);
        fma2(acc0, ap, wv.x);
        fma2(acc1, ap, wv.y);
    }
    float4 bb = *(const float4*)&bo[cb + cg * 4];
    float2 a01 = upk2(acc0), a23 = upk2(acc1);
    const float is2 = 0.70710678118654752f;
    float x;
    float4 o;
    x = a01.x + bb.x; o.x = 0.5f * x * (1.f + erff(x * is2));
    x = a01.y + bb.y; o.y = 0.5f * x * (1.f + erff(x * is2));
    x = a23.x + bb.z; o.z = 0.5f * x * (1.f + erff(x * is2));
    x = a23.y + bb.w; o.w = 0.5f * x * (1.f + erff(x * is2));
    *(float4*)&g_comb[(size_t)(row0 + rg) * 256 + cb + cg * 4] = o;
}

// ---------------------------------------------------------------------------
// K7b: val/gate = comb @ Wsk + bsk; out = nf*(1-g) + val*g.
// grid = (128 rowtiles, 2 colhalves of 128), block = 256.  Each block computes
// BOTH the val strip (cols ch*128..) and the matching gate strip (+256).
// ---------------------------------------------------------------------------
__global__ void k_out2(const float* __restrict__ Wsk, const float* __restrict__ bsk,
                       const float* __restrict__ nf, float* __restrict__ out) {
    __shared__ float cs[8 * 256];
    int row0 = blockIdx.x * 8;
    int ch = blockIdx.y * 128;
    int t = threadIdx.x;
    const float4* src = (const float4*)(g_comb + (size_t)row0 * 256);
    float4* dst = (float4*)cs;
    #pragma unroll
    for (int i = t; i < 512; i += 256) dst[i] = src[i];
    __syncthreads();

    int cg = t & 31;   // cols ch + cg*4
    int rg = t >> 5;   // one row
    ull av0 = 0ULL, av1 = 0ULL, ag0 = 0ULL, ag1 = 0ULL;
    #pragma unroll 4
    for (int k = 0; k < 256; k++) {
        ulonglong2 wv = *(const ulonglong2*)&Wsk[k * 512 + ch + cg * 4];
        ulonglong2 wg = *(const ulonglong2*)&Wsk[k * 512 + 256 + ch + cg * 4];
        float a = cs[rg * 256 + k];
        ull ap = pk2(a, a);
        fma2(av0, ap, wv.x);
        fma2(av1, ap, wv.y);
        fma2(ag0, ap, wg.x);
        fma2(ag1, ap, wg.y);
    }
    float4 bv = *(const float4*)&bsk[ch + cg * 4];
    float4 bg = *(const float4*)&bsk[256 + ch + cg * 4];
    float2 v01 = upk2(av0), v23 = upk2(av1);
    float2 g01 = upk2(ag0), g23 = upk2(ag1);
    float val[4], gat[4];
    val[0] = v01.x + bv.x; val[1] = v01.y + bv.y; val[2] = v23.x + bv.z; val[3] = v23.y + bv.w;
    gat[0] = g01.x + bg.x; gat[1] = g01.y + bg.y; gat[2] = g23.x + bg.z; gat[3] = g23.y + bg.w;
    size_t idx = (size_t)(row0 + rg) * 256 + ch + cg * 4;
    float4 nfv = *(const float4*)&nf[idx];
    float4 o;
    float g;
    g = 1.0f / (1.0f + __expf(-gat[0])); o.x = nfv.x * (1.0f - g) + val[0] * g;
    g = 1.0f / (1.0f + __expf(-gat[1])); o.y = nfv.y * (1.0f - g) + val[1] * g;
    g = 1.0f / (1.0f + __expf(-gat[2])); o.z = nfv.z * (1.0f - g) + val[2] * g;
    g = 1.0f / (1.0f + __expf(-gat[3])); o.w = nfv.w * (1.0f - g) + val[3] * g;
    *(float4*)&out[idx] = o;
}

// ---------------------------------------------------------------------------
extern "C" void kernel_launch(void* const* d_in, const int* in_sizes, int n_in,
                              void* d_out, int out_size) {
    const float* node_feat = (const float*)d_in[0];
    const float* edge_feat = (const float*)d_in[1];
    const int* x_idx1 = (const int*)d_in[2];
    const int* x_idx2 = (const int*)d_in[3];
    const float* mask_valid = (const float*)d_in[4];
    const float* Wqkv = (const float*)d_in[5];
    const float* bqkv = (const float*)d_in[6];
    const float* Wev  = (const float*)d_in[7];
    const float* bev  = (const float*)d_in[8];
    const float* Wea  = (const float*)d_in[9];
    const float* bea  = (const float*)d_in[10];
    const float* Wo   = (const float*)d_in[11];
    const float* bo   = (const float*)d_in[12];
    const float* Wsk  = (const float*)d_in[13];
    const float* bsk  = (const float*)d_in[14];
    const float* gn   = (const float*)d_in[15];
    const float* bn   = (const float*)d_in[16];
    const float* ge   = (const float*)d_in[17];
    const float* be   = (const float*)d_in[18];
    float* out = (float*)d_out;

    k_node_ln<<<1024, 256>>>(node_feat, gn, bn);
    k_qkv<<<dim3(64, 3), 256>>>(Wqkv, bqkv);
    k_edge<<<1016, 256>>>(edge_feat, ge, be, Wea, bea, x_idx1, x_idx2, mask_valid);
    k_lsm<<<256, 256>>>();
    k_agg<<<1024, 256>>>();
    k_proj<<<256, 256>>>(Wev, bev);
    k_out1<<<dim3(128, 2), 256>>>(Wo, bo);
    k_out2<<<dim3(128, 2), 256>>>(Wsk, bsk, node_feat, out);
}

// round 10
// speedup vs baseline: 1.2506x; 1.2506x over previous
#include <cuda_runtime.h>
#include <math.h>

// Problem constants
#define BB 8
#define NN 128
#define HN_ 256
#define HE_ 128
#define NH 8
#define DH_ 32
#define PP 8128
#define BP 65024   // B * P

typedef unsigned long long ull;

__device__ __forceinline__ ull pk2(float x, float y) {
    ull r; asm("mov.b64 %0,{%1,%2};" : "=l"(r) : "f"(x), "f"(y)); return r;
}
__device__ __forceinline__ float2 upk2(ull v) {
    float2 f; asm("mov.b64 {%0,%1},%2;" : "=f"(f.x), "=f"(f.y) : "l"(v)); return f;
}
// d = a*b + d  (packed f32x2 FFMA) — used ONLY where operands are pre-packed
__device__ __forceinline__ void fma2(ull& d, ull a, ull b) {
    asm("fma.rn.f32x2 %0,%1,%2,%0;" : "+l"(d) : "l"(a), "l"(b));
}

// Scratch (no cudaMalloc allowed -> __device__ globals)
__device__ float g_n_in[1024 * 256];     // [B*N, HN]
__device__ float g_qkv[1024 * 768];      // [B*N, 3*HN]
__device__ float g_e_in[BP * 128];       // [B*P, HE]
__device__ float g_att[64 * 128 * 128];  // [B*H, N, N] adj -> probs (in place)
__device__ float g_aggE[1024 * 8 * 128]; // [B*N, H, HE]
__device__ float g_anyv[1024];           // [B*N]
__device__ float g_attn[1024 * 256];     // [B*N, HN]
__device__ float g_comb[1024 * 256];     // [B*N, HN]

__device__ __forceinline__ int pair_idx(int i, int j) {
    if (i > j) { int t = i; i = j; j = t; }
    return i * (255 - i) / 2 + (j - i - 1);
}

// ---------------------------------------------------------------------------
// K1: node LayerNorm.  grid = 1024, block = 256   [R8 version]
// ---------------------------------------------------------------------------
__global__ void k_node_ln(const float* __restrict__ nf,
                          const float* __restrict__ gn,
                          const float* __restrict__ bn) {
    int row = blockIdx.x;
    int t = threadIdx.x;
    float x = nf[row * 256 + t];
    float s = x, s2 = x * x;
    #pragma unroll
    for (int o = 16; o; o >>= 1) {
        s  += __shfl_xor_sync(0xFFFFFFFFu, s,  o);
        s2 += __shfl_xor_sync(0xFFFFFFFFu, s2, o);
    }
    __shared__ float rs_[8], rs2_[8];
    int w = t >> 5, l = t & 31;
    if (l == 0) { rs_[w] = s; rs2_[w] = s2; }
    __syncthreads();
    float tot = 0.f, tot2 = 0.f;
    #pragma unroll
    for (int i = 0; i < 8; i++) { tot += rs_[i]; tot2 += rs2_[i]; }
    float mean = tot * (1.0f / 256.0f);
    float var  = tot2 * (1.0f / 256.0f) - mean * mean;
    float rstd = rsqrtf(var + 1e-5f);
    g_n_in[row * 256 + t] = (x - mean) * rstd * gn[t] + bn[t];
}

// ---------------------------------------------------------------------------
// K2: qkv GEMM. n_in[1024,256] @ Wqkv[256,768]. grid=(64,3), block=256.
// [R8 scalar version]
// ---------------------------------------------------------------------------
__global__ void k_qkv(const float* __restrict__ W, const float* __restrict__ bias) {
    __shared__ float As[16 * 256];
    int t = threadIdx.x;
    int row0 = blockIdx.x * 16;
    int cb = blockIdx.y * 256;
    const float4* a4 = (const float4*)(g_n_in + row0 * 256);
    float4* s4 = (float4*)As;
    #pragma unroll
    for (int i = t; i < 1024; i += 256) s4[i] = a4[i];
    __syncthreads();
    int cg = t & 63;
    int rg = t >> 6;
    float4 acc[4];
    #pragma unroll
    for (int r = 0; r < 4; r++) acc[r] = make_float4(0.f, 0.f, 0.f, 0.f);
    for (int k = 0; k < 256; k++) {
        float4 w = *(const float4*)&W[k * 768 + cb + cg * 4];
        #pragma unroll
        for (int r = 0; r < 4; r++) {
            float a = As[(rg * 4 + r) * 256 + k];
            acc[r].x += a * w.x; acc[r].y += a * w.y;
            acc[r].z += a * w.z; acc[r].w += a * w.w;
        }
    }
    float4 bb = *(const float4*)&bias[cb + cg * 4];
    #pragma unroll
    for (int r = 0; r < 4; r++) {
        float4 o;
        o.x = acc[r].x + bb.x; o.y = acc[r].y + bb.y;
        o.z = acc[r].z + bb.z; o.w = acc[r].w + bb.w;
        *(float4*)&g_qkv[(row0 + rg * 4 + r) * 768 + cb + cg * 4] = o;
    }
}

// ---------------------------------------------------------------------------
// K3: edge LayerNorm + e_adj scatter into g_att.  [R8 version]
// grid = 1016 (64 edge rows per block), block = 256.
// ---------------------------------------------------------------------------
__global__ void k_edge(const float* __restrict__ ef,
                       const float* __restrict__ ge, const float* __restrict__ be,
                       const float* __restrict__ Wea, const float* __restrict__ bea,
                       const int* __restrict__ i1, const int* __restrict__ i2,
                       const float* __restrict__ mask) {
    __shared__ float es[64 * 132];
    __shared__ float wa[128 * 8];
    __shared__ float ges[128], bes[128];
    __shared__ int s_i[64], s_j[64];
    __shared__ float s_mask[64];
    int t = threadIdx.x;
    int base_row = blockIdx.x * 64;
    int b = base_row / 8128;
    int p0 = base_row - b * 8128;
    int base = base_row * 128;

    float4* es4 = (float4*)es;
    const float4* ef4 = (const float4*)(ef + base);
    #pragma unroll
    for (int i = t; i < 2048; i += 256) es4[(i >> 5) * 33 + (i & 31)] = ef4[i];
    for (int i = t; i < 1024; i += 256) wa[i] = Wea[i];
    if (t < 128) { ges[t] = ge[t]; bes[t] = be[t]; }
    if (t < 64) {
        int p = p0 + t;
        s_i[t] = i1[p]; s_j[t] = i2[p];
        s_mask[t] = mask[b * PP + p];
    }
    __syncthreads();

    int w = t >> 5, l = t & 31;
    #pragma unroll
    for (int rr = 0; rr < 8; rr++) {
        int r = w * 8 + rr;
        float4 v = *(float4*)&es[r * 132 + l * 4];
        float s  = v.x + v.y + v.z + v.w;
        float s2 = v.x * v.x + v.y * v.y + v.z * v.z + v.w * v.w;
        #pragma unroll
        for (int o = 16; o; o >>= 1) {
            s  += __shfl_xor_sync(0xFFFFFFFFu, s,  o);
            s2 += __shfl_xor_sync(0xFFFFFFFFu, s2, o);
        }
        float mean = s * (1.0f / 128.0f);
        float var  = s2 * (1.0f / 128.0f) - mean * mean;
        float rstd = rsqrtf(var + 1e-5f);
        int c = l * 4;
        float4 o4;
        o4.x = (v.x - mean) * rstd * ges[c + 0] + bes[c + 0];
        o4.y = (v.y - mean) * rstd * ges[c + 1] + bes[c + 1];
        o4.z = (v.z - mean) * rstd * ges[c + 2] + bes[c + 2];
        o4.w = (v.w - mean) * rstd * ges[c + 3] + bes[c + 3];
        *(float4*)&es[r * 132 + c] = o4;
    }
    __syncthreads();

    float4* out4 = (float4*)(g_e_in + base);
    #pragma unroll
    for (int i = t; i < 2048; i += 256) out4[i] = es4[(i >> 5) * 33 + (i & 31)];

    // e_adj: thread = (row r, head pair q) -> 2 heads, float4 es reads
    {
        int r = t >> 2, q = t & 3;
        float s0 = 0.f, s1 = 0.f;
        #pragma unroll 8
        for (int c4 = 0; c4 < 32; c4++) {
            float4 e4 = *(float4*)&es[r * 132 + c4 * 4];
            int c = c4 * 4;
            float2 w0 = *(float2*)&wa[(c + 0) * 8 + q * 2];
            float2 w1 = *(float2*)&wa[(c + 1) * 8 + q * 2];
            float2 w2 = *(float2*)&wa[(c + 2) * 8 + q * 2];
            float2 w3 = *(float2*)&wa[(c + 3) * 8 + q * 2];
            s0 += e4.x * w0.x + e4.y * w1.x + e4.z * w2.x + e4.w * w3.x;
            s1 += e4.x * w0.y + e4.y * w1.y + e4.z * w2.y + e4.w * w3.y;
        }
        float m = s_mask[r];
        float v0 = (m == 0.f) ? -1e20f : (s0 + bea[q * 2]);
        float v1 = (m == 0.f) ? -1e20f : (s1 + bea[q * 2 + 1]);
        int ni = s_i[r], nj = s_j[r];
        float* Ab0 = g_att + (size_t)(b * 8 + q * 2) * 16384;
        float* Ab1 = Ab0 + 16384;
        Ab0[ni * 128 + nj] = v0;
        Ab0[nj * 128 + ni] = v0;
        Ab1[ni * 128 + nj] = v1;
        Ab1[nj * 128 + ni] = v1;
    }
}

// ---------------------------------------------------------------------------
// K4: fused logits + softmax + P@V.  [R9 version — measured faster]
// grid = 256 (b, h, n-quarter of 32 rows), block = 256.
// ---------------------------------------------------------------------------
__global__ void k_lsm() {
    int bx = blockIdx.x;
    int b = bx >> 5, h = (bx >> 2) & 7, nq = bx & 3;
    int n0 = nq * 32;
    __shared__ float Qs[32 * 36];
    __shared__ float KV[128 * 36];   // first Ks_t[k*132+m], then Vs[m*36+d]
    __shared__ float Ps[32 * 132];
    int t = threadIdx.x;

    {   // Q rows n0..n0+31 : exactly one float4 per thread
        int n = t >> 3, f = t & 7;
        float4 q = *(const float4*)&g_qkv[(size_t)(b * 128 + n0 + n) * 768 + h * 32 + f * 4];
        *(float4*)&Qs[n * 36 + f * 4] = q;
    }
    #pragma unroll
    for (int i = t; i < 1024; i += 256) {   // K transposed store
        int m = i >> 3, f = i & 7;
        float4 kk = *(const float4*)&g_qkv[(size_t)(b * 128 + m) * 768 + 256 + h * 32 + f * 4];
        KV[(f * 4 + 0) * 132 + m] = kk.x;
        KV[(f * 4 + 1) * 132 + m] = kk.y;
        KV[(f * 4 + 2) * 132 + m] = kk.z;
        KV[(f * 4 + 3) * 132 + m] = kk.w;
    }
    __syncthreads();

    int n_g = t >> 5;   // warp id = query-row group (4 rows)
    int m_g = t & 31;   // lane = key group (4 keys)
    ull acc2[4][2];
    #pragma unroll
    for (int i = 0; i < 4; i++) { acc2[i][0] = 0ULL; acc2[i][1] = 0ULL; }

    #pragma unroll 8
    for (int k = 0; k < 32; k++) {
        ulonglong2 kv = *(const ulonglong2*)&KV[k * 132 + m_g * 4];
        #pragma unroll
        for (int i = 0; i < 4; i++) {
            float q = Qs[(n_g * 4 + i) * 36 + k];
            ull qp = pk2(q, q);
            fma2(acc2[i][0], qp, kv.x);
            fma2(acc2[i][1], qp, kv.y);
        }
    }

    const float scale = 0.17677669529663687f;  // 1/sqrt(32)
    float* Lb = g_att + (size_t)(b * 8 + h) * 16384;
    #pragma unroll
    for (int i = 0; i < 4; i++) {
        int n = n0 + n_g * 4 + i;
        float2 a01 = upk2(acc2[i][0]), a23 = upk2(acc2[i][1]);
        float4 adj = *(const float4*)&Lb[n * 128 + m_g * 4];
        float lg[4];
        lg[0] = (n == m_g * 4 + 0) ? -1e20f : fmaf(a01.x, scale, adj.x);
        lg[1] = (n == m_g * 4 + 1) ? -1e20f : fmaf(a01.y, scale, adj.y);
        lg[2] = (n == m_g * 4 + 2) ? -1e20f : fmaf(a23.x, scale, adj.z);
        lg[3] = (n == m_g * 4 + 3) ? -1e20f : fmaf(a23.y, scale, adj.w);
        float mx = fmaxf(fmaxf(lg[0], lg[1]), fmaxf(lg[2], lg[3]));
        #pragma unroll
        for (int o = 16; o; o >>= 1) mx = fmaxf(mx, __shfl_xor_sync(0xFFFFFFFFu, mx, o));
        float anyv = (mx > -1e19f) ? 1.f : 0.f;
        float e0 = __expf(lg[0] - mx), e1 = __expf(lg[1] - mx);
        float e2 = __expf(lg[2] - mx), e3 = __expf(lg[3] - mx);
        float sum = e0 + e1 + e2 + e3;
        #pragma unroll
        for (int o = 16; o; o >>= 1) sum += __shfl_xor_sync(0xFFFFFFFFu, sum, o);
        float inv = anyv / sum;
        float4 p = make_float4(e0 * inv, e1 * inv, e2 * inv, e3 * inv);
        *(float4*)&Ps[(n_g * 4 + i) * 132 + m_g * 4] = p;
        *(float4*)&Lb[n * 128 + m_g * 4] = p;
        if (m_g == 0) g_anyv[b * 128 + n] = anyv;
    }
    __syncthreads();

    // stage V into KV (natural layout [m][36])
    #pragma unroll
    for (int i = t; i < 1024; i += 256) {
        int m = i >> 3, f = i & 7;
        float4 v = *(const float4*)&g_qkv[(size_t)(b * 128 + m) * 768 + 512 + h * 32 + f * 4];
        *(float4*)&KV[m * 36 + f * 4] = v;
    }
    __syncthreads();

    // P @ V : thread = (row group ng2, dim d); 4 rows each
    {
        int d = t & 31, ng2 = t >> 5;
        float a2[4];
        #pragma unroll
        for (int j = 0; j < 4; j++) a2[j] = 0.f;
        #pragma unroll 4
        for (int m = 0; m < 128; m++) {
            float v = KV[m * 36 + d];
            #pragma unroll
            for (int j = 0; j < 4; j++) a2[j] += Ps[(ng2 + 8 * j) * 132 + m] * v;
        }
        #pragma unroll
        for (int j = 0; j < 4; j++) {
            int n = n0 + ng2 + 8 * j;
            g_attn[(size_t)(b * 128 + n) * 256 + h * 32 + d] = a2[j];
        }
    }
}

// ---------------------------------------------------------------------------
// K5: e_in aggregation over neighbors (probs read from g_att).
// grid = 1024 (one (b,n)), block = 256.  SCALAR math.
// Thread = (col-float4 cg 0..31, m-split ms 0..7): each ev float4 feeds ALL 8
// heads -> gather L1 transactions /4 vs R8.
// ---------------------------------------------------------------------------
__global__ void k_agg() {
    int bx = blockIdx.x;
    int b = bx >> 7, n = bx & 127;
    int t = threadIdx.x;
    int cg = t & 31, ms = t >> 5;

    __shared__ float ps[8 * 128];
    __shared__ int pidx_s[128];
    __shared__ float psum[64 * 128];   // [ms*8+h][128]

    if (t < 128) pidx_s[t] = (t == n) ? 0 : pair_idx(n, t);
    {   // load probs: 8 heads x 128, one float4 per thread
        int hh = t >> 5, mg = t & 31;
        const float* Lb = g_att + ((size_t)(b * 8 + hh) * 128 + n) * 128;
        *(float4*)&ps[hh * 128 + mg * 4] = *(const float4*)&Lb[mg * 4];
    }
    __syncthreads();

    int pbase = b * PP;
    float4 acc[8];
    #pragma unroll
    for (int hh = 0; hh < 8; hh++) acc[hh] = make_float4(0.f, 0.f, 0.f, 0.f);

    int mbeg = ms * 16;
    #pragma unroll 2
    for (int mm = 0; mm < 16; mm++) {
        int m = mbeg + mm;
        float4 ev = *(const float4*)&g_e_in[(size_t)(pbase + pidx_s[m]) * 128 + cg * 4];
        #pragma unroll
        for (int hh = 0; hh < 8; hh++) {
            float pr = ps[hh * 128 + m];
            acc[hh].x += pr * ev.x; acc[hh].y += pr * ev.y;
            acc[hh].z += pr * ev.z; acc[hh].w += pr * ev.w;
        }
    }
    #pragma unroll
    for (int hh = 0; hh < 8; hh++)
        *(float4*)&psum[(ms * 8 + hh) * 128 + cg * 4] = acc[hh];
    __syncthreads();

    // reduce the 8 m-splits
    int hh = t >> 5, cc = t & 31;
    float4 o = make_float4(0.f, 0.f, 0.f, 0.f);
    #pragma unroll
    for (int s = 0; s < 8; s++) {
        float4 r = *(float4*)&psum[(s * 8 + hh) * 128 + cc * 4];
        o.x += r.x; o.y += r.y; o.z += r.z; o.w += r.w;
    }
    *(float4*)&g_aggE[(size_t)bx * 1024 + hh * 128 + cc * 4] = o;
}

// ---------------------------------------------------------------------------
// K6: g_attn += aggE @ Wev + anyv * bev.  grid = 256 (4 rows), block = 256.
// [R8 scalar version]
// ---------------------------------------------------------------------------
__global__ void k_proj(const float* __restrict__ Wev, const float* __restrict__ bev) {
    __shared__ float aE[4 * 1024];
    int t = threadIdx.x;
    int row0 = blockIdx.x * 4;
    const float4* src = (const float4*)(g_aggE + (size_t)row0 * 1024);
    float4* dst = (float4*)aE;
    #pragma unroll
    for (int i = t; i < 1024; i += 256) dst[i] = src[i];
    __syncthreads();

    int h = t >> 5;
    float acc[4];
    #pragma unroll
    for (int r = 0; r < 4; r++) acc[r] = 0.f;
    #pragma unroll 4
    for (int c = 0; c < 128; c++) {
        float w = Wev[c * 256 + t];
        #pragma unroll
        for (int r = 0; r < 4; r++) acc[r] += aE[r * 1024 + h * 128 + c] * w;
    }
    float bv = bev[t];
    #pragma unroll
    for (int r = 0; r < 4; r++) {
        int bn = row0 + r;
        float any = g_anyv[bn];
        g_attn[(size_t)bn * 256 + t] += acc[r] + any * bv;
    }
}

// ---------------------------------------------------------------------------
// K7a: comb = gelu(cat(n_in,attn)@Wo+bo).  grid = (128 rowtiles, 2 colhalves),
// block = 256.  8 rows/block, 128 cols/block.  SCALAR float4 FMA.
// ---------------------------------------------------------------------------
__global__ void k_out1(const float* __restrict__ Wo, const float* __restrict__ bo) {
    __shared__ float cs[8 * 512];
    int row0 = blockIdx.x * 8;
    int cb = blockIdx.y * 128;
    int t = threadIdx.x;
    #pragma unroll
    for (int i = t; i < 1024; i += 256) {
        int r = i >> 7, f = i & 127;
        float4 v = (f < 64)
            ? *(const float4*)&g_n_in[(size_t)(row0 + r) * 256 + f * 4]
            : *(const float4*)&g_attn[(size_t)(row0 + r) * 256 + (f - 64) * 4];
        *(float4*)&cs[r * 512 + f * 4] = v;
    }
    __syncthreads();

    int cg = t & 31;   // cols cb + cg*4
    int rg = t >> 5;   // one row
    float4 acc = make_float4(0.f, 0.f, 0.f, 0.f);
    #pragma unroll 4
    for (int k = 0; k < 512; k++) {
        float4 w = *(const float4*)&Wo[k * 256 + cb + cg * 4];
        float a = cs[rg * 512 + k];
        acc.x += a * w.x; acc.y += a * w.y; acc.z += a * w.z; acc.w += a * w.w;
    }
    float4 bb = *(const float4*)&bo[cb + cg * 4];
    const float is2 = 0.70710678118654752f;
    float x;
    float4 o;
    x = acc.x + bb.x; o.x = 0.5f * x * (1.f + erff(x * is2));
    x = acc.y + bb.y; o.y = 0.5f * x * (1.f + erff(x * is2));
    x = acc.z + bb.z; o.z = 0.5f * x * (1.f + erff(x * is2));
    x = acc.w + bb.w; o.w = 0.5f * x * (1.f + erff(x * is2));
    *(float4*)&g_comb[(size_t)(row0 + rg) * 256 + cb + cg * 4] = o;
}

// ---------------------------------------------------------------------------
// K7b: val/gate = comb @ Wsk + bsk; out = nf*(1-g) + val*g.
// grid = (128 rowtiles, 2 colhalves of 128), block = 256.  SCALAR float4 FMA.
// Each block computes BOTH the val strip and the matching gate strip (+256).
// ---------------------------------------------------------------------------
__global__ void k_out2(const float* __restrict__ Wsk, const float* __restrict__ bsk,
                       const float* __restrict__ nf, float* __restrict__ out) {
    __shared__ float cs[8 * 256];
    int row0 = blockIdx.x * 8;
    int ch = blockIdx.y * 128;
    int t = threadIdx.x;
    const float4* src = (const float4*)(g_comb + (size_t)row0 * 256);
    float4* dst = (float4*)cs;
    #pragma unroll
    for (int i = t; i < 512; i += 256) dst[i] = src[i];
    __syncthreads();

    int cg = t & 31;   // cols ch + cg*4
    int rg = t >> 5;   // one row
    float4 av = make_float4(0.f, 0.f, 0.f, 0.f);
    float4 ag = make_float4(0.f, 0.f, 0.f, 0.f);
    #pragma unroll 4
    for (int k = 0; k < 256; k++) {
        float4 wv = *(const float4*)&Wsk[k * 512 + ch + cg * 4];
        float4 wg = *(const float4*)&Wsk[k * 512 + 256 + ch + cg * 4];
        float a = cs[rg * 256 + k];
        av.x += a * wv.x; av.y += a * wv.y; av.z += a * wv.z; av.w += a * wv.w;
        ag.x += a * wg.x; ag.y += a * wg.y; ag.z += a * wg.z; ag.w += a * wg.w;
    }
    float4 bv = *(const float4*)&bsk[ch + cg * 4];
    float4 bg = *(const float4*)&bsk[256 + ch + cg * 4];
    float val[4], gat[4];
    val[0] = av.x + bv.x; val[1] = av.y + bv.y; val[2] = av.z + bv.z; val[3] = av.w + bv.w;
    gat[0] = ag.x + bg.x; gat[1] = ag.y + bg.y; gat[2] = ag.z + bg.z; gat[3] = ag.w + bg.w;
    size_t idx = (size_t)(row0 + rg) * 256 + ch + cg * 4;
    float4 nfv = *(const float4*)&nf[idx];
    float4 o;
    float g;
    g = 1.0f / (1.0f + __expf(-gat[0])); o.x = nfv.x * (1.0f - g) + val[0] * g;
    g = 1.0f / (1.0f + __expf(-gat[1])); o.y = nfv.y * (1.0f - g) + val[1] * g;
    g = 1.0f / (1.0f + __expf(-gat[2])); o.z = nfv.z * (1.0f - g) + val[2] * g;
    g = 1.0f / (1.0f + __expf(-gat[3])); o.w = nfv.w * (1.0f - g) + val[3] * g;
    *(float4*)&out[idx] = o;
}

// ---------------------------------------------------------------------------
extern "C" void kernel_launch(void* const* d_in, const int* in_sizes, int n_in,
                              void* d_out, int out_size) {
    const float* node_feat = (const float*)d_in[0];
    const float* edge_feat = (const float*)d_in[1];
    const int* x_idx1 = (const int*)d_in[2];
    const int* x_idx2 = (const int*)d_in[3];
    const float* mask_valid = (const float*)d_in[4];
    const float* Wqkv = (const float*)d_in[5];
    const float* bqkv = (const float*)d_in[6];
    const float* Wev  = (const float*)d_in[7];
    const float* bev  = (const float*)d_in[8];
    const float* Wea  = (const float*)d_in[9];
    const float* bea  = (const float*)d_in[10];
    const float* Wo   = (const float*)d_in[11];
    const float* bo   = (const float*)d_in[12];
    const float* Wsk  = (const float*)d_in[13];
    const float* bsk  = (const float*)d_in[14];
    const float* gn   = (const float*)d_in[15];
    const float* bn   = (const float*)d_in[16];
    const float* ge   = (const float*)d_in[17];
    const float* be   = (const float*)d_in[18];
    float* out = (float*)d_out;

    k_node_ln<<<1024, 256>>>(node_feat, gn, bn);
    k_qkv<<<dim3(64, 3), 256>>>(Wqkv, bqkv);
    k_edge<<<1016, 256>>>(edge_feat, ge, be, Wea, bea, x_idx1, x_idx2, mask_valid);
    k_lsm<<<256, 256>>>();
    k_agg<<<1024, 256>>>();
    k_proj<<<256, 256>>>(Wev, bev);
    k_out1<<<dim3(128, 2), 256>>>(Wo, bo);
    k_out2<<<dim3(128, 2), 256>>>(Wsk, bsk, node_feat, out);
}

// round 11
// speedup vs baseline: 1.2531x; 1.0020x over previous
#include <cuda_runtime.h>
#include <math.h>

// Problem constants
#define BB 8
#define NN 128
#define HN_ 256
#define HE_ 128
#define NH 8
#define DH_ 32
#define PP 8128
#define BP 65024   // B * P

typedef unsigned long long ull;

__device__ __forceinline__ ull pk2(float x, float y) {
    ull r; asm("mov.b64 %0,{%1,%2};" : "=l"(r) : "f"(x), "f"(y)); return r;
}
__device__ __forceinline__ float2 upk2(ull v) {
    float2 f; asm("mov.b64 {%0,%1},%2;" : "=f"(f.x), "=f"(f.y) : "l"(v)); return f;
}
// d = a*b + d  (packed f32x2 FFMA) — only where operands are pre-packed (k_lsm)
__device__ __forceinline__ void fma2(ull& d, ull a, ull b) {
    asm("fma.rn.f32x2 %0,%1,%2,%0;" : "+l"(d) : "l"(a), "l"(b));
}

// Scratch (no cudaMalloc allowed -> __device__ globals)
__device__ float g_n_in[1024 * 256];     // [B*N, HN]
__device__ float g_qkv[1024 * 768];      // [B*N, 3*HN]
__device__ float g_e_in[BP * 128];       // [B*P, HE]
__device__ float g_att[64 * 128 * 128];  // [B*H, N, N] adj -> probs (in place)
__device__ float g_aggE[1024 * 8 * 128]; // [B*N, H, HE]
__device__ float g_anyv[1024];           // [B*N]
__device__ float g_attn[1024 * 256];     // [B*N, HN]

__device__ __forceinline__ int pair_idx(int i, int j) {
    if (i > j) { int t = i; i = j; j = t; }
    return i * (255 - i) / 2 + (j - i - 1);
}

// ---------------------------------------------------------------------------
// K1: node LayerNorm.  grid = 1024, block = 256   [R8]
// ---------------------------------------------------------------------------
__global__ void k_node_ln(const float* __restrict__ nf,
                          const float* __restrict__ gn,
                          const float* __restrict__ bn) {
    int row = blockIdx.x;
    int t = threadIdx.x;
    float x = nf[row * 256 + t];
    float s = x, s2 = x * x;
    #pragma unroll
    for (int o = 16; o; o >>= 1) {
        s  += __shfl_xor_sync(0xFFFFFFFFu, s,  o);
        s2 += __shfl_xor_sync(0xFFFFFFFFu, s2, o);
    }
    __shared__ float rs_[8], rs2_[8];
    int w = t >> 5, l = t & 31;
    if (l == 0) { rs_[w] = s; rs2_[w] = s2; }
    __syncthreads();
    float tot = 0.f, tot2 = 0.f;
    #pragma unroll
    for (int i = 0; i < 8; i++) { tot += rs_[i]; tot2 += rs2_[i]; }
    float mean = tot * (1.0f / 256.0f);
    float var  = tot2 * (1.0f / 256.0f) - mean * mean;
    float rstd = rsqrtf(var + 1e-5f);
    g_n_in[row * 256 + t] = (x - mean) * rstd * gn[t] + bn[t];
}

// ---------------------------------------------------------------------------
// K2: qkv GEMM. grid=(64,3), block=256.  [R8 scalar]
// ---------------------------------------------------------------------------
__global__ void k_qkv(const float* __restrict__ W, const float* __restrict__ bias) {
    __shared__ float As[16 * 256];
    int t = threadIdx.x;
    int row0 = blockIdx.x * 16;
    int cb = blockIdx.y * 256;
    const float4* a4 = (const float4*)(g_n_in + row0 * 256);
    float4* s4 = (float4*)As;
    #pragma unroll
    for (int i = t; i < 1024; i += 256) s4[i] = a4[i];
    __syncthreads();
    int cg = t & 63;
    int rg = t >> 6;
    float4 acc[4];
    #pragma unroll
    for (int r = 0; r < 4; r++) acc[r] = make_float4(0.f, 0.f, 0.f, 0.f);
    for (int k = 0; k < 256; k++) {
        float4 w = *(const float4*)&W[k * 768 + cb + cg * 4];
        #pragma unroll
        for (int r = 0; r < 4; r++) {
            float a = As[(rg * 4 + r) * 256 + k];
            acc[r].x += a * w.x; acc[r].y += a * w.y;
            acc[r].z += a * w.z; acc[r].w += a * w.w;
        }
    }
    float4 bb = *(const float4*)&bias[cb + cg * 4];
    #pragma unroll
    for (int r = 0; r < 4; r++) {
        float4 o;
        o.x = acc[r].x + bb.x; o.y = acc[r].y + bb.y;
        o.z = acc[r].z + bb.z; o.w = acc[r].w + bb.w;
        *(float4*)&g_qkv[(row0 + rg * 4 + r) * 768 + cb + cg * 4] = o;
    }
}

// ---------------------------------------------------------------------------
// K3: edge LayerNorm + e_adj scatter into g_att.  [R8]
// grid = 1016 (64 edge rows per block), block = 256.
// ---------------------------------------------------------------------------
__global__ void k_edge(const float* __restrict__ ef,
                       const float* __restrict__ ge, const float* __restrict__ be,
                       const float* __restrict__ Wea, const float* __restrict__ bea,
                       const int* __restrict__ i1, const int* __restrict__ i2,
                       const float* __restrict__ mask) {
    __shared__ float es[64 * 132];
    __shared__ float wa[128 * 8];
    __shared__ float ges[128], bes[128];
    __shared__ int s_i[64], s_j[64];
    __shared__ float s_mask[64];
    int t = threadIdx.x;
    int base_row = blockIdx.x * 64;
    int b = base_row / 8128;
    int p0 = base_row - b * 8128;
    int base = base_row * 128;

    float4* es4 = (float4*)es;
    const float4* ef4 = (const float4*)(ef + base);
    #pragma unroll
    for (int i = t; i < 2048; i += 256) es4[(i >> 5) * 33 + (i & 31)] = ef4[i];
    for (int i = t; i < 1024; i += 256) wa[i] = Wea[i];
    if (t < 128) { ges[t] = ge[t]; bes[t] = be[t]; }
    if (t < 64) {
        int p = p0 + t;
        s_i[t] = i1[p]; s_j[t] = i2[p];
        s_mask[t] = mask[b * PP + p];
    }
    __syncthreads();

    int w = t >> 5, l = t & 31;
    #pragma unroll
    for (int rr = 0; rr < 8; rr++) {
        int r = w * 8 + rr;
        float4 v = *(float4*)&es[r * 132 + l * 4];
        float s  = v.x + v.y + v.z + v.w;
        float s2 = v.x * v.x + v.y * v.y + v.z * v.z + v.w * v.w;
        #pragma unroll
        for (int o = 16; o; o >>= 1) {
            s  += __shfl_xor_sync(0xFFFFFFFFu, s,  o);
            s2 += __shfl_xor_sync(0xFFFFFFFFu, s2, o);
        }
        float mean = s * (1.0f / 128.0f);
        float var  = s2 * (1.0f / 128.0f) - mean * mean;
        float rstd = rsqrtf(var + 1e-5f);
        int c = l * 4;
        float4 o4;
        o4.x = (v.x - mean) * rstd * ges[c + 0] + bes[c + 0];
        o4.y = (v.y - mean) * rstd * ges[c + 1] + bes[c + 1];
        o4.z = (v.z - mean) * rstd * ges[c + 2] + bes[c + 2];
        o4.w = (v.w - mean) * rstd * ges[c + 3] + bes[c + 3];
        *(float4*)&es[r * 132 + c] = o4;
    }
    __syncthreads();

    float4* out4 = (float4*)(g_e_in + base);
    #pragma unroll
    for (int i = t; i < 2048; i += 256) out4[i] = es4[(i >> 5) * 33 + (i & 31)];

    {
        int r = t >> 2, q = t & 3;
        float s0 = 0.f, s1 = 0.f;
        #pragma unroll 8
        for (int c4 = 0; c4 < 32; c4++) {
            float4 e4 = *(float4*)&es[r * 132 + c4 * 4];
            int c = c4 * 4;
            float2 w0 = *(float2*)&wa[(c + 0) * 8 + q * 2];
            float2 w1 = *(float2*)&wa[(c + 1) * 8 + q * 2];
            float2 w2 = *(float2*)&wa[(c + 2) * 8 + q * 2];
            float2 w3 = *(float2*)&wa[(c + 3) * 8 + q * 2];
            s0 += e4.x * w0.x + e4.y * w1.x + e4.z * w2.x + e4.w * w3.x;
            s1 += e4.x * w0.y + e4.y * w1.y + e4.z * w2.y + e4.w * w3.y;
        }
        float m = s_mask[r];
        float v0 = (m == 0.f) ? -1e20f : (s0 + bea[q * 2]);
        float v1 = (m == 0.f) ? -1e20f : (s1 + bea[q * 2 + 1]);
        int ni = s_i[r], nj = s_j[r];
        float* Ab0 = g_att + (size_t)(b * 8 + q * 2) * 16384;
        float* Ab1 = Ab0 + 16384;
        Ab0[ni * 128 + nj] = v0;
        Ab0[nj * 128 + ni] = v0;
        Ab1[ni * 128 + nj] = v1;
        Ab1[nj * 128 + ni] = v1;
    }
}

// ---------------------------------------------------------------------------
// K4: fused logits + softmax + P@V.  [R9 — measured best]
// grid = 256 (b, h, n-quarter of 32 rows), block = 256.
// ---------------------------------------------------------------------------
__global__ void k_lsm() {
    int bx = blockIdx.x;
    int b = bx >> 5, h = (bx >> 2) & 7, nq = bx & 3;
    int n0 = nq * 32;
    __shared__ float Qs[32 * 36];
    __shared__ float KV[128 * 36];
    __shared__ float Ps[32 * 132];
    int t = threadIdx.x;

    {
        int n = t >> 3, f = t & 7;
        float4 q = *(const float4*)&g_qkv[(size_t)(b * 128 + n0 + n) * 768 + h * 32 + f * 4];
        *(float4*)&Qs[n * 36 + f * 4] = q;
    }
    #pragma unroll
    for (int i = t; i < 1024; i += 256) {
        int m = i >> 3, f = i & 7;
        float4 kk = *(const float4*)&g_qkv[(size_t)(b * 128 + m) * 768 + 256 + h * 32 + f * 4];
        KV[(f * 4 + 0) * 132 + m] = kk.x;
        KV[(f * 4 + 1) * 132 + m] = kk.y;
        KV[(f * 4 + 2) * 132 + m] = kk.z;
        KV[(f * 4 + 3) * 132 + m] = kk.w;
    }
    __syncthreads();

    int n_g = t >> 5;
    int m_g = t & 31;
    ull acc2[4][2];
    #pragma unroll
    for (int i = 0; i < 4; i++) { acc2[i][0] = 0ULL; acc2[i][1] = 0ULL; }

    #pragma unroll 8
    for (int k = 0; k < 32; k++) {
        ulonglong2 kv = *(const ulonglong2*)&KV[k * 132 + m_g * 4];
        #pragma unroll
        for (int i = 0; i < 4; i++) {
            float q = Qs[(n_g * 4 + i) * 36 + k];
            ull qp = pk2(q, q);
            fma2(acc2[i][0], qp, kv.x);
            fma2(acc2[i][1], qp, kv.y);
        }
    }

    const float scale = 0.17677669529663687f;
    float* Lb = g_att + (size_t)(b * 8 + h) * 16384;
    #pragma unroll
    for (int i = 0; i < 4; i++) {
        int n = n0 + n_g * 4 + i;
        float2 a01 = upk2(acc2[i][0]), a23 = upk2(acc2[i][1]);
        float4 adj = *(const float4*)&Lb[n * 128 + m_g * 4];
        float lg[4];
        lg[0] = (n == m_g * 4 + 0) ? -1e20f : fmaf(a01.x, scale, adj.x);
        lg[1] = (n == m_g * 4 + 1) ? -1e20f : fmaf(a01.y, scale, adj.y);
        lg[2] = (n == m_g * 4 + 2) ? -1e20f : fmaf(a23.x, scale, adj.z);
        lg[3] = (n == m_g * 4 + 3) ? -1e20f : fmaf(a23.y, scale, adj.w);
        float mx = fmaxf(fmaxf(lg[0], lg[1]), fmaxf(lg[2], lg[3]));
        #pragma unroll
        for (int o = 16; o; o >>= 1) mx = fmaxf(mx, __shfl_xor_sync(0xFFFFFFFFu, mx, o));
        float anyv = (mx > -1e19f) ? 1.f : 0.f;
        float e0 = __expf(lg[0] - mx), e1 = __expf(lg[1] - mx);
        float e2 = __expf(lg[2] - mx), e3 = __expf(lg[3] - mx);
        float sum = e0 + e1 + e2 + e3;
        #pragma unroll
        for (int o = 16; o; o >>= 1) sum += __shfl_xor_sync(0xFFFFFFFFu, sum, o);
        float inv = anyv / sum;
        float4 p = make_float4(e0 * inv, e1 * inv, e2 * inv, e3 * inv);
        *(float4*)&Ps[(n_g * 4 + i) * 132 + m_g * 4] = p;
        *(float4*)&Lb[n * 128 + m_g * 4] = p;
        if (m_g == 0) g_anyv[b * 128 + n] = anyv;
    }
    __syncthreads();

    #pragma unroll
    for (int i = t; i < 1024; i += 256) {
        int m = i >> 3, f = i & 7;
        float4 v = *(const float4*)&g_qkv[(size_t)(b * 128 + m) * 768 + 512 + h * 32 + f * 4];
        *(float4*)&KV[m * 36 + f * 4] = v;
    }
    __syncthreads();

    {
        int d = t & 31, ng2 = t >> 5;
        float a2[4];
        #pragma unroll
        for (int j = 0; j < 4; j++) a2[j] = 0.f;
        #pragma unroll 4
        for (int m = 0; m < 128; m++) {
            float v = KV[m * 36 + d];
            #pragma unroll
            for (int j = 0; j < 4; j++) a2[j] += Ps[(ng2 + 8 * j) * 132 + m] * v;
        }
        #pragma unroll
        for (int j = 0; j < 4; j++) {
            int n = n0 + ng2 + 8 * j;
            g_attn[(size_t)(b * 128 + n) * 256 + h * 32 + d] = a2[j];
        }
    }
}

// ---------------------------------------------------------------------------
// K5: e_in aggregation (probs from g_att).  [R8 — 2-way m-split]
// grid = 1024, block = 256.
// ---------------------------------------------------------------------------
__global__ void k_agg() {
    int bx = blockIdx.x;
    int b = bx >> 7, n = bx & 127;
    int t = threadIdx.x;

    __shared__ float ps[8 * 128];
    __shared__ int pidx_s[128];
    __shared__ float psum[2 * 8 * 128];

    if (t < 128) pidx_s[t] = (t == n) ? 0 : pair_idx(n, t);
    {
        int hh = t >> 5, mg = t & 31;
        const float* Lb = g_att + ((size_t)(b * 8 + hh) * 128 + n) * 128;
        *(float4*)&ps[hh * 128 + mg * 4] = *(const float4*)&Lb[mg * 4];
    }
    __syncthreads();

    int cg = t & 31;
    int g2 = t >> 5;
    int hp = (g2 & 3) * 2;
    int ms = g2 >> 2;
    int pbase = b * PP;
    float4 a0 = make_float4(0.f, 0.f, 0.f, 0.f);
    float4 a1 = make_float4(0.f, 0.f, 0.f, 0.f);
    int mbeg = ms * 64;
    #pragma unroll 4
    for (int mm = 0; mm < 64; mm++) {
        int m = mbeg + mm;
        const float4 ev = *(const float4*)&g_e_in[(size_t)(pbase + pidx_s[m]) * 128 + cg * 4];
        float p0 = ps[hp * 128 + m];
        float p1 = ps[(hp + 1) * 128 + m];
        a0.x += p0 * ev.x; a0.y += p0 * ev.y; a0.z += p0 * ev.z; a0.w += p0 * ev.w;
        a1.x += p1 * ev.x; a1.y += p1 * ev.y; a1.z += p1 * ev.z; a1.w += p1 * ev.w;
    }
    *(float4*)&psum[(ms * 8 + hp) * 128 + cg * 4] = a0;
    *(float4*)&psum[(ms * 8 + hp + 1) * 128 + cg * 4] = a1;
    __syncthreads();

    int hh = t >> 5, cc = t & 31;
    float4 r0 = *(float4*)&psum[(hh * 128) + cc * 4];
    float4 r1 = *(float4*)&psum[((8 + hh) * 128) + cc * 4];
    float4 o;
    o.x = r0.x + r1.x; o.y = r0.y + r1.y; o.z = r0.z + r1.z; o.w = r0.w + r1.w;
    *(float4*)&g_aggE[(size_t)bx * 1024 + hh * 128 + cc * 4] = o;
}

// ---------------------------------------------------------------------------
// K6: g_attn += aggE @ Wev + anyv * bev.  grid = 256 (4 rows), block = 256. [R8]
// ---------------------------------------------------------------------------
__global__ void k_proj(const float* __restrict__ Wev, const float* __restrict__ bev) {
    __shared__ float aE[4 * 1024];
    int t = threadIdx.x;
    int row0 = blockIdx.x * 4;
    const float4* src = (const float4*)(g_aggE + (size_t)row0 * 1024);
    float4* dst = (float4*)aE;
    #pragma unroll
    for (int i = t; i < 1024; i += 256) dst[i] = src[i];
    __syncthreads();

    int h = t >> 5;
    float acc[4];
    #pragma unroll
    for (int r = 0; r < 4; r++) acc[r] = 0.f;
    #pragma unroll 4
    for (int c = 0; c < 128; c++) {
        float w = Wev[c * 256 + t];
        #pragma unroll
        for (int r = 0; r < 4; r++) acc[r] += aE[r * 1024 + h * 128 + c] * w;
    }
    float bv = bev[t];
    #pragma unroll
    for (int r = 0; r < 4; r++) {
        int bn = row0 + r;
        float any = g_anyv[bn];
        g_attn[(size_t)bn * 256 + t] += acc[r] + any * bv;
    }
}

// ---------------------------------------------------------------------------
// K7: fused output (NEW: 8 rows/block, grid 128 — halves Wo/Wsk L2 traffic).
// comb = gelu(cat(n_in,attn)@Wo+bo) kept in smem;
// val/gate = comb@Wsk+bsk computed in the SAME thread (no vg exchange);
// out = nf*(1-g) + val*g.
// ---------------------------------------------------------------------------
__global__ void k_out(const float* __restrict__ Wo, const float* __restrict__ bo,
                      const float* __restrict__ Wsk, const float* __restrict__ bsk,
                      const float* __restrict__ nf, float* __restrict__ out) {
    __shared__ float cs[8 * 512];     // 16KB
    __shared__ float comb[8 * 256];   // 8KB
    int row0 = blockIdx.x * 8;
    int t = threadIdx.x;
    #pragma unroll
    for (int i = t; i < 1024; i += 256) {
        int r = i >> 7, f = i & 127;
        float4 v = (f < 64)
            ? *(const float4*)&g_n_in[(size_t)(row0 + r) * 256 + f * 4]
            : *(const float4*)&g_attn[(size_t)(row0 + r) * 256 + (f - 64) * 4];
        *(float4*)&cs[r * 512 + f * 4] = v;
    }
    __syncthreads();

    // GEMM1: thread = (rows rg*2, rg*2+1; cols cg*4). 8 FMA per weight-float4.
    {
        int cg = t & 63, rg = t >> 6;
        float4 acc0 = make_float4(0.f, 0.f, 0.f, 0.f);
        float4 acc1 = make_float4(0.f, 0.f, 0.f, 0.f);
        const float* c0 = &cs[(rg * 2) * 512];
        const float* c1 = &cs[(rg * 2 + 1) * 512];
        #pragma unroll 4
        for (int k = 0; k < 512; k++) {
            float4 w = *(const float4*)&Wo[k * 256 + cg * 4];
            float a0 = c0[k], a1 = c1[k];
            acc0.x += a0 * w.x; acc0.y += a0 * w.y; acc0.z += a0 * w.z; acc0.w += a0 * w.w;
            acc1.x += a1 * w.x; acc1.y += a1 * w.y; acc1.z += a1 * w.z; acc1.w += a1 * w.w;
        }
        float4 bb = *(const float4*)&bo[cg * 4];
        const float is2 = 0.70710678118654752f;
        float x;
        float4 o0, o1;
        x = acc0.x + bb.x; o0.x = 0.5f * x * (1.f + erff(x * is2));
        x = acc0.y + bb.y; o0.y = 0.5f * x * (1.f + erff(x * is2));
        x = acc0.z + bb.z; o0.z = 0.5f * x * (1.f + erff(x * is2));
        x = acc0.w + bb.w; o0.w = 0.5f * x * (1.f + erff(x * is2));
        x = acc1.x + bb.x; o1.x = 0.5f * x * (1.f + erff(x * is2));
        x = acc1.y + bb.y; o1.y = 0.5f * x * (1.f + erff(x * is2));
        x = acc1.z + bb.z; o1.z = 0.5f * x * (1.f + erff(x * is2));
        x = acc1.w + bb.w; o1.w = 0.5f * x * (1.f + erff(x * is2));
        *(float4*)&comb[(rg * 2) * 256 + cg * 4] = o0;
        *(float4*)&comb[(rg * 2 + 1) * 256 + cg * 4] = o1;
    }
    __syncthreads();

    // GEMM2: thread = (rows rp*2, rp*2+1; val cols cg*4, gate cols 256+cg*4).
    // 16 FMA per 2 weight-float4s; sigmoid+blend in registers.
    {
        int cg = t & 63, rp = t >> 6;
        float4 av0 = make_float4(0.f, 0.f, 0.f, 0.f);
        float4 av1 = make_float4(0.f, 0.f, 0.f, 0.f);
        float4 ag0 = make_float4(0.f, 0.f, 0.f, 0.f);
        float4 ag1 = make_float4(0.f, 0.f, 0.f, 0.f);
        const float* c0 = &comb[(rp * 2) * 256];
        const float* c1 = &comb[(rp * 2 + 1) * 256];
        #pragma unroll 4
        for (int k = 0; k < 256; k++) {
            float4 wv = *(const float4*)&Wsk[k * 512 + cg * 4];
            float4 wg = *(const float4*)&Wsk[k * 512 + 256 + cg * 4];
            float a0 = c0[k], a1 = c1[k];
            av0.x += a0 * wv.x; av0.y += a0 * wv.y; av0.z += a0 * wv.z; av0.w += a0 * wv.w;
            av1.x += a1 * wv.x; av1.y += a1 * wv.y; av1.z += a1 * wv.z; av1.w += a1 * wv.w;
            ag0.x += a0 * wg.x; ag0.y += a0 * wg.y; ag0.z += a0 * wg.z; ag0.w += a0 * wg.w;
            ag1.x += a1 * wg.x; ag1.y += a1 * wg.y; ag1.z += a1 * wg.z; ag1.w += a1 * wg.w;
        }
        float4 bv = *(const float4*)&bsk[cg * 4];
        float4 bg = *(const float4*)&bsk[256 + cg * 4];
        #pragma unroll
        for (int r = 0; r < 2; r++) {
            float4 av = r ? av1 : av0;
            float4 ag = r ? ag1 : ag0;
            size_t idx = (size_t)(row0 + rp * 2 + r) * 256 + cg * 4;
            float4 nfv = *(const float4*)&nf[idx];
            float val, gat, g;
            float4 o;
            val = av.x + bv.x; gat = ag.x + bg.x;
            g = 1.0f / (1.0f + __expf(-gat)); o.x = nfv.x * (1.0f - g) + val * g;
            val = av.y + bv.y; gat = ag.y + bg.y;
            g = 1.0f / (1.0f + __expf(-gat)); o.y = nfv.y * (1.0f - g) + val * g;
            val = av.z + bv.z; gat = ag.z + bg.z;
            g = 1.0f / (1.0f + __expf(-gat)); o.z = nfv.z * (1.0f - g) + val * g;
            val = av.w + bv.w; gat = ag.w + bg.w;
            g = 1.0f / (1.0f + __expf(-gat)); o.w = nfv.w * (1.0f - g) + val * g;
            *(float4*)&out[idx] = o;
        }
    }
}

// ---------------------------------------------------------------------------
extern "C" void kernel_launch(void* const* d_in, const int* in_sizes, int n_in,
                              void* d_out, int out_size) {
    const float* node_feat = (const float*)d_in[0];
    const float* edge_feat = (const float*)d_in[1];
    const int* x_idx1 = (const int*)d_in[2];
    const int* x_idx2 = (const int*)d_in[3];
    const float* mask_valid = (const float*)d_in[4];
    const float* Wqkv = (const float*)d_in[5];
    const float* bqkv = (const float*)d_in[6];
    const float* Wev  = (const float*)d_in[7];
    const float* bev  = (const float*)d_in[8];
    const float* Wea  = (const float*)d_in[9];
    const float* bea  = (const float*)d_in[10];
    const float* Wo   = (const float*)d_in[11];
    const float* bo   = (const float*)d_in[12];
    const float* Wsk  = (const float*)d_in[13];
    const float* bsk  = (const float*)d_in[14];
    const float* gn   = (const float*)d_in[15];
    const float* bn   = (const float*)d_in[16];
    const float* ge   = (const float*)d_in[17];
    const float* be   = (const float*)d_in[18];
    float* out = (float*)d_out;

    k_node_ln<<<1024, 256>>>(node_feat, gn, bn);
    k_qkv<<<dim3(64, 3), 256>>>(Wqkv, bqkv);
    k_edge<<<1016, 256>>>(edge_feat, ge, be, Wea, bea, x_idx1, x_idx2, mask_valid);
    k_lsm<<<256, 256>>>();
    k_agg<<<1024, 256>>>();
    k_proj<<<256, 256>>>(Wev, bev);
    k_out<<<128, 256>>>(Wo, bo, Wsk, bsk, node_feat, out);
}

// round 12
// speedup vs baseline: 1.4864x; 1.1862x over previous
#include <cuda_runtime.h>
#include <math.h>

// Problem constants
#define BB 8
#define NN 128
#define HN_ 256
#define HE_ 128
#define NH 8
#define DH_ 32
#define PP 8128
#define BP 65024   // B * P

typedef unsigned long long ull;

__device__ __forceinline__ ull pk2(float x, float y) {
    ull r; asm("mov.b64 %0,{%1,%2};" : "=l"(r) : "f"(x), "f"(y)); return r;
}
__device__ __forceinline__ float2 upk2(ull v) {
    float2 f; asm("mov.b64 {%0,%1},%2;" : "=f"(f.x), "=f"(f.y) : "l"(v)); return f;
}
// d = a*b + d  (packed f32x2 FFMA) — only where operands are pre-packed (k_lsm)
__device__ __forceinline__ void fma2(ull& d, ull a, ull b) {
    asm("fma.rn.f32x2 %0,%1,%2,%0;" : "+l"(d) : "l"(a), "l"(b));
}

// Scratch (no cudaMalloc allowed -> __device__ globals)
__device__ float g_n_in[1024 * 256];     // [B*N, HN]
__device__ float g_qkv[1024 * 768];      // [B*N, 3*HN]
__device__ float g_e_in[BP * 128];       // [B*P, HE]
__device__ float g_att[64 * 128 * 128];  // [B*H, N, N] adj -> probs (in place)
__device__ float g_anyv[1024];           // [B*N]
__device__ float g_attn[1024 * 256];     // [B*N, HN]

__device__ __forceinline__ int pair_idx(int i, int j) {
    if (i > j) { int t = i; i = j; j = t; }
    return i * (255 - i) / 2 + (j - i - 1);
}

// ---------------------------------------------------------------------------
// K1: node LayerNorm.  grid = 1024, block = 256   [R8]
// ---------------------------------------------------------------------------
__global__ void k_node_ln(const float* __restrict__ nf,
                          const float* __restrict__ gn,
                          const float* __restrict__ bn) {
    int row = blockIdx.x;
    int t = threadIdx.x;
    float x = nf[row * 256 + t];
    float s = x, s2 = x * x;
    #pragma unroll
    for (int o = 16; o; o >>= 1) {
        s  += __shfl_xor_sync(0xFFFFFFFFu, s,  o);
        s2 += __shfl_xor_sync(0xFFFFFFFFu, s2, o);
    }
    __shared__ float rs_[8], rs2_[8];
    int w = t >> 5, l = t & 31;
    if (l == 0) { rs_[w] = s; rs2_[w] = s2; }
    __syncthreads();
    float tot = 0.f, tot2 = 0.f;
    #pragma unroll
    for (int i = 0; i < 8; i++) { tot += rs_[i]; tot2 += rs2_[i]; }
    float mean = tot * (1.0f / 256.0f);
    float var  = tot2 * (1.0f / 256.0f) - mean * mean;
    float rstd = rsqrtf(var + 1e-5f);
    g_n_in[row * 256 + t] = (x - mean) * rstd * gn[t] + bn[t];
}

// ---------------------------------------------------------------------------
// K2: qkv GEMM. grid=(64,3), block=256.  [R8 scalar]
// ---------------------------------------------------------------------------
__global__ void k_qkv(const float* __restrict__ W, const float* __restrict__ bias) {
    __shared__ float As[16 * 256];
    int t = threadIdx.x;
    int row0 = blockIdx.x * 16;
    int cb = blockIdx.y * 256;
    const float4* a4 = (const float4*)(g_n_in + row0 * 256);
    float4* s4 = (float4*)As;
    #pragma unroll
    for (int i = t; i < 1024; i += 256) s4[i] = a4[i];
    __syncthreads();
    int cg = t & 63;
    int rg = t >> 6;
    float4 acc[4];
    #pragma unroll
    for (int r = 0; r < 4; r++) acc[r] = make_float4(0.f, 0.f, 0.f, 0.f);
    for (int k = 0; k < 256; k++) {
        float4 w = *(const float4*)&W[k * 768 + cb + cg * 4];
        #pragma unroll
        for (int r = 0; r < 4; r++) {
            float a = As[(rg * 4 + r) * 256 + k];
            acc[r].x += a * w.x; acc[r].y += a * w.y;
            acc[r].z += a * w.z; acc[r].w += a * w.w;
        }
    }
    float4 bb = *(const float4*)&bias[cb + cg * 4];
    #pragma unroll
    for (int r = 0; r < 4; r++) {
        float4 o;
        o.x = acc[r].x + bb.x; o.y = acc[r].y + bb.y;
        o.z = acc[r].z + bb.z; o.w = acc[r].w + bb.w;
        *(float4*)&g_qkv[(row0 + rg * 4 + r) * 768 + cb + cg * 4] = o;
    }
}

// ---------------------------------------------------------------------------
// K3: edge LayerNorm + e_adj scatter into g_att.  [R8]
// grid = 1016 (64 edge rows per block), block = 256.
// ---------------------------------------------------------------------------
__global__ void k_edge(const float* __restrict__ ef,
                       const float* __restrict__ ge, const float* __restrict__ be,
                       const float* __restrict__ Wea, const float* __restrict__ bea,
                       const int* __restrict__ i1, const int* __restrict__ i2,
                       const float* __restrict__ mask) {
    __shared__ float es[64 * 132];
    __shared__ float wa[128 * 8];
    __shared__ float ges[128], bes[128];
    __shared__ int s_i[64], s_j[64];
    __shared__ float s_mask[64];
    int t = threadIdx.x;
    int base_row = blockIdx.x * 64;
    int b = base_row / 8128;
    int p0 = base_row - b * 8128;
    int base = base_row * 128;

    float4* es4 = (float4*)es;
    const float4* ef4 = (const float4*)(ef + base);
    #pragma unroll
    for (int i = t; i < 2048; i += 256) es4[(i >> 5) * 33 + (i & 31)] = ef4[i];
    for (int i = t; i < 1024; i += 256) wa[i] = Wea[i];
    if (t < 128) { ges[t] = ge[t]; bes[t] = be[t]; }
    if (t < 64) {
        int p = p0 + t;
        s_i[t] = i1[p]; s_j[t] = i2[p];
        s_mask[t] = mask[b * PP + p];
    }
    __syncthreads();

    int w = t >> 5, l = t & 31;
    #pragma unroll
    for (int rr = 0; rr < 8; rr++) {
        int r = w * 8 + rr;
        float4 v = *(float4*)&es[r * 132 + l * 4];
        float s  = v.x + v.y + v.z + v.w;
        float s2 = v.x * v.x + v.y * v.y + v.z * v.z + v.w * v.w;
        #pragma unroll
        for (int o = 16; o; o >>= 1) {
            s  += __shfl_xor_sync(0xFFFFFFFFu, s,  o);
            s2 += __shfl_xor_sync(0xFFFFFFFFu, s2, o);
        }
        float mean = s * (1.0f / 128.0f);
        float var  = s2 * (1.0f / 128.0f) - mean * mean;
        float rstd = rsqrtf(var + 1e-5f);
        int c = l * 4;
        float4 o4;
        o4.x = (v.x - mean) * rstd * ges[c + 0] + bes[c + 0];
        o4.y = (v.y - mean) * rstd * ges[c + 1] + bes[c + 1];
        o4.z = (v.z - mean) * rstd * ges[c + 2] + bes[c + 2];
        o4.w = (v.w - mean) * rstd * ges[c + 3] + bes[c + 3];
        *(float4*)&es[r * 132 + c] = o4;
    }
    __syncthreads();

    float4* out4 = (float4*)(g_e_in + base);
    #pragma unroll
    for (int i = t; i < 2048; i += 256) out4[i] = es4[(i >> 5) * 33 + (i & 31)];

    {
        int r = t >> 2, q = t & 3;
        float s0 = 0.f, s1 = 0.f;
        #pragma unroll 8
        for (int c4 = 0; c4 < 32; c4++) {
            float4 e4 = *(float4*)&es[r * 132 + c4 * 4];
            int c = c4 * 4;
            float2 w0 = *(float2*)&wa[(c + 0) * 8 + q * 2];
            float2 w1 = *(float2*)&wa[(c + 1) * 8 + q * 2];
            float2 w2 = *(float2*)&wa[(c + 2) * 8 + q * 2];
            float2 w3 = *(float2*)&wa[(c + 3) * 8 + q * 2];
            s0 += e4.x * w0.x + e4.y * w1.x + e4.z * w2.x + e4.w * w3.x;
            s1 += e4.x * w0.y + e4.y * w1.y + e4.z * w2.y + e4.w * w3.y;
        }
        float m = s_mask[r];
        float v0 = (m == 0.f) ? -1e20f : (s0 + bea[q * 2]);
        float v1 = (m == 0.f) ? -1e20f : (s1 + bea[q * 2 + 1]);
        int ni = s_i[r], nj = s_j[r];
        float* Ab0 = g_att + (size_t)(b * 8 + q * 2) * 16384;
        float* Ab1 = Ab0 + 16384;
        Ab0[ni * 128 + nj] = v0;
        Ab0[nj * 128 + ni] = v0;
        Ab1[ni * 128 + nj] = v1;
        Ab1[nj * 128 + ni] = v1;
    }
}

// ---------------------------------------------------------------------------
// K4: fused logits + softmax + P@V.  [R9 — per-kernel measured best]
// grid = 256 (b, h, n-quarter of 32 rows), block = 256.
// ---------------------------------------------------------------------------
__global__ void k_lsm() {
    int bx = blockIdx.x;
    int b = bx >> 5, h = (bx >> 2) & 7, nq = bx & 3;
    int n0 = nq * 32;
    __shared__ float Qs[32 * 36];
    __shared__ float KV[128 * 36];
    __shared__ float Ps[32 * 132];
    int t = threadIdx.x;

    {
        int n = t >> 3, f = t & 7;
        float4 q = *(const float4*)&g_qkv[(size_t)(b * 128 + n0 + n) * 768 + h * 32 + f * 4];
        *(float4*)&Qs[n * 36 + f * 4] = q;
    }
    #pragma unroll
    for (int i = t; i < 1024; i += 256) {
        int m = i >> 3, f = i & 7;
        float4 kk = *(const float4*)&g_qkv[(size_t)(b * 128 + m) * 768 + 256 + h * 32 + f * 4];
        KV[(f * 4 + 0) * 132 + m] = kk.x;
        KV[(f * 4 + 1) * 132 + m] = kk.y;
        KV[(f * 4 + 2) * 132 + m] = kk.z;
        KV[(f * 4 + 3) * 132 + m] = kk.w;
    }
    __syncthreads();

    int n_g = t >> 5;
    int m_g = t & 31;
    ull acc2[4][2];
    #pragma unroll
    for (int i = 0; i < 4; i++) { acc2[i][0] = 0ULL; acc2[i][1] = 0ULL; }

    #pragma unroll 8
    for (int k = 0; k < 32; k++) {
        ulonglong2 kv = *(const ulonglong2*)&KV[k * 132 + m_g * 4];
        #pragma unroll
        for (int i = 0; i < 4; i++) {
            float q = Qs[(n_g * 4 + i) * 36 + k];
            ull qp = pk2(q, q);
            fma2(acc2[i][0], qp, kv.x);
            fma2(acc2[i][1], qp, kv.y);
        }
    }

    const float scale = 0.17677669529663687f;
    float* Lb = g_att + (size_t)(b * 8 + h) * 16384;
    #pragma unroll
    for (int i = 0; i < 4; i++) {
        int n = n0 + n_g * 4 + i;
        float2 a01 = upk2(acc2[i][0]), a23 = upk2(acc2[i][1]);
        float4 adj = *(const float4*)&Lb[n * 128 + m_g * 4];
        float lg[4];
        lg[0] = (n == m_g * 4 + 0) ? -1e20f : fmaf(a01.x, scale, adj.x);
        lg[1] = (n == m_g * 4 + 1) ? -1e20f : fmaf(a01.y, scale, adj.y);
        lg[2] = (n == m_g * 4 + 2) ? -1e20f : fmaf(a23.x, scale, adj.z);
        lg[3] = (n == m_g * 4 + 3) ? -1e20f : fmaf(a23.y, scale, adj.w);
        float mx = fmaxf(fmaxf(lg[0], lg[1]), fmaxf(lg[2], lg[3]));
        #pragma unroll
        for (int o = 16; o; o >>= 1) mx = fmaxf(mx, __shfl_xor_sync(0xFFFFFFFFu, mx, o));
        float anyv = (mx > -1e19f) ? 1.f : 0.f;
        float e0 = __expf(lg[0] - mx), e1 = __expf(lg[1] - mx);
        float e2 = __expf(lg[2] - mx), e3 = __expf(lg[3] - mx);
        float sum = e0 + e1 + e2 + e3;
        #pragma unroll
        for (int o = 16; o; o >>= 1) sum += __shfl_xor_sync(0xFFFFFFFFu, sum, o);
        float inv = anyv / sum;
        float4 p = make_float4(e0 * inv, e1 * inv, e2 * inv, e3 * inv);
        *(float4*)&Ps[(n_g * 4 + i) * 132 + m_g * 4] = p;
        *(float4*)&Lb[n * 128 + m_g * 4] = p;
        if (m_g == 0) g_anyv[b * 128 + n] = anyv;
    }
    __syncthreads();

    #pragma unroll
    for (int i = t; i < 1024; i += 256) {
        int m = i >> 3, f = i & 7;
        float4 v = *(const float4*)&g_qkv[(size_t)(b * 128 + m) * 768 + 512 + h * 32 + f * 4];
        *(float4*)&KV[m * 36 + f * 4] = v;
    }
    __syncthreads();

    {
        int d = t & 31, ng2 = t >> 5;
        float a2[4];
        #pragma unroll
        for (int j = 0; j < 4; j++) a2[j] = 0.f;
        #pragma unroll 4
        for (int m = 0; m < 128; m++) {
            float v = KV[m * 36 + d];
            #pragma unroll
            for (int j = 0; j < 4; j++) a2[j] += Ps[(ng2 + 8 * j) * 132 + m] * v;
        }
        #pragma unroll
        for (int j = 0; j < 4; j++) {
            int n = n0 + ng2 + 8 * j;
            g_attn[(size_t)(b * 128 + n) * 256 + h * 32 + d] = a2[j];
        }
    }
}

// ---------------------------------------------------------------------------
// K5: MERGED e_in aggregation + Wev projection.
// grid = 1024 (one (b,n)), block = 256.
// Phase 1 = R8 k_agg (2-way m-split, aggE kept in smem).
// Phase 2 = g_attn += aggE @ Wev + anyv * bev  (Wev is 128KB -> L1-resident).
// Kills the 4MB g_aggE round-trip and the k_proj launch.
// ---------------------------------------------------------------------------
__global__ void k_aggp(const float* __restrict__ Wev, const float* __restrict__ bev) {
    int bx = blockIdx.x;
    int b = bx >> 7, n = bx & 127;
    int t = threadIdx.x;

    __shared__ float ps[8 * 128];
    __shared__ int pidx_s[128];
    __shared__ float psum[2 * 8 * 128];
    __shared__ float aE[8 * 128];

    if (t < 128) pidx_s[t] = (t == n) ? 0 : pair_idx(n, t);
    {
        int hh = t >> 5, mg = t & 31;
        const float* Lb = g_att + ((size_t)(b * 8 + hh) * 128 + n) * 128;
        *(float4*)&ps[hh * 128 + mg * 4] = *(const float4*)&Lb[mg * 4];
    }
    __syncthreads();

    int cg = t & 31;
    int g2 = t >> 5;
    int hp = (g2 & 3) * 2;
    int ms = g2 >> 2;
    int pbase = b * PP;
    float4 a0 = make_float4(0.f, 0.f, 0.f, 0.f);
    float4 a1 = make_float4(0.f, 0.f, 0.f, 0.f);
    int mbeg = ms * 64;
    #pragma unroll 4
    for (int mm = 0; mm < 64; mm++) {
        int m = mbeg + mm;
        const float4 ev = *(const float4*)&g_e_in[(size_t)(pbase + pidx_s[m]) * 128 + cg * 4];
        float p0 = ps[hp * 128 + m];
        float p1 = ps[(hp + 1) * 128 + m];
        a0.x += p0 * ev.x; a0.y += p0 * ev.y; a0.z += p0 * ev.z; a0.w += p0 * ev.w;
        a1.x += p1 * ev.x; a1.y += p1 * ev.y; a1.z += p1 * ev.z; a1.w += p1 * ev.w;
    }
    *(float4*)&psum[(ms * 8 + hp) * 128 + cg * 4] = a0;
    *(float4*)&psum[(ms * 8 + hp + 1) * 128 + cg * 4] = a1;
    __syncthreads();

    {   // reduce the 2 m-splits into aE
        int hh = t >> 5, cc = t & 31;
        float4 r0 = *(float4*)&psum[(hh * 128) + cc * 4];
        float4 r1 = *(float4*)&psum[((8 + hh) * 128) + cc * 4];
        float4 o;
        o.x = r0.x + r1.x; o.y = r0.y + r1.y; o.z = r0.z + r1.z; o.w = r0.w + r1.w;
        *(float4*)&aE[hh * 128 + cc * 4] = o;
    }
    __syncthreads();

    // Phase 2: projection.  t = output column = h*32+d.
    {
        int h = t >> 5;
        const float* row = &aE[h * 128];
        float acc = 0.f;
        #pragma unroll 8
        for (int c = 0; c < 128; c++) acc += row[c] * Wev[c * 256 + t];
        float any = g_anyv[bx];
        g_attn[(size_t)bx * 256 + t] += acc + any * bev[t];
    }
}

// ---------------------------------------------------------------------------
// K6: fused output.  [EXACT R8 version — grid 256, 4 rows/block]
// ---------------------------------------------------------------------------
__global__ void k_out(const float* __restrict__ Wo, const float* __restrict__ bo,
                      const float* __restrict__ Wsk, const float* __restrict__ bsk,
                      const float* __restrict__ nf, float* __restrict__ out) {
    __shared__ float cs[4 * 512];
    __shared__ float comb[4 * 256];
    __shared__ float vg[4 * 512];
    int row0 = blockIdx.x * 4;
    int t = threadIdx.x;
    #pragma unroll
    for (int i = t; i < 512; i += 256) {
        int r = i >> 7, f = i & 127;
        float4 v = (f < 64)
            ? *(const float4*)&g_n_in[(size_t)(row0 + r) * 256 + f * 4]
            : *(const float4*)&g_attn[(size_t)(row0 + r) * 256 + (f - 64) * 4];
        *(float4*)&cs[r * 512 + f * 4] = v;
    }
    __syncthreads();

    // GEMM1: 4 rows x 256 cols; thread = (row rg, 4 cols)
    {
        int cg = t & 63, rg = t >> 6;
        float4 acc = make_float4(0.f, 0.f, 0.f, 0.f);
        for (int k = 0; k < 512; k++) {
            float4 w = *(const float4*)&Wo[k * 256 + cg * 4];
            float a = cs[rg * 512 + k];
            acc.x += a * w.x; acc.y += a * w.y; acc.z += a * w.z; acc.w += a * w.w;
        }
        float4 bb = *(const float4*)&bo[cg * 4];
        const float is2 = 0.70710678118654752f;
        float x;
        float4 o;
        x = acc.x + bb.x; o.x = 0.5f * x * (1.f + erff(x * is2));
        x = acc.y + bb.y; o.y = 0.5f * x * (1.f + erff(x * is2));
        x = acc.z + bb.z; o.z = 0.5f * x * (1.f + erff(x * is2));
        x = acc.w + bb.w; o.w = 0.5f * x * (1.f + erff(x * is2));
        *(float4*)&comb[rg * 256 + cg * 4] = o;
    }
    __syncthreads();

    // GEMM2: 4 rows x 512 cols; thread = (2 rows, 4 cols)
    {
        int cg = t & 127, rg = t >> 7;
        float4 acc0 = make_float4(0.f, 0.f, 0.f, 0.f);
        float4 acc1 = make_float4(0.f, 0.f, 0.f, 0.f);
        for (int k = 0; k < 256; k++) {
            float4 w = *(const float4*)&Wsk[k * 512 + cg * 4];
            float a0 = comb[(rg * 2) * 256 + k];
            float a1 = comb[(rg * 2 + 1) * 256 + k];
            acc0.x += a0 * w.x; acc0.y += a0 * w.y; acc0.z += a0 * w.z; acc0.w += a0 * w.w;
            acc1.x += a1 * w.x; acc1.y += a1 * w.y; acc1.z += a1 * w.z; acc1.w += a1 * w.w;
        }
        float4 bb = *(const float4*)&bsk[cg * 4];
        float4 o0, o1;
        o0.x = acc0.x + bb.x; o0.y = acc0.y + bb.y; o0.z = acc0.z + bb.z; o0.w = acc0.w + bb.w;
        o1.x = acc1.x + bb.x; o1.y = acc1.y + bb.y; o1.z = acc1.z + bb.z; o1.w = acc1.w + bb.w;
        *(float4*)&vg[(rg * 2) * 512 + cg * 4] = o0;
        *(float4*)&vg[(rg * 2 + 1) * 512 + cg * 4] = o1;
    }
    __syncthreads();

    #pragma unroll
    for (int r = 0; r < 4; r++) {
        float val  = vg[r * 512 + t];
        float gate = vg[r * 512 + 256 + t];
        float g = 1.0f / (1.0f + __expf(-gate));
        size_t idx = (size_t)(row0 + r) * 256 + t;
        out[idx] = nf[idx] * (1.0f - g) + val * g;
    }
}

// ---------------------------------------------------------------------------
extern "C" void kernel_launch(void* const* d_in, const int* in_sizes, int n_in,
                              void* d_out, int out_size) {
    const float* node_feat = (const float*)d_in[0];
    const float* edge_feat = (const float*)d_in[1];
    const int* x_idx1 = (const int*)d_in[2];
    const int* x_idx2 = (const int*)d_in[3];
    const float* mask_valid = (const float*)d_in[4];
    const float* Wqkv = (const float*)d_in[5];
    const float* bqkv = (const float*)d_in[6];
    const float* Wev  = (const float*)d_in[7];
    const float* bev  = (const float*)d_in[8];
    const float* Wea  = (const float*)d_in[9];
    const float* bea  = (const float*)d_in[10];
    const float* Wo   = (const float*)d_in[11];
    const float* bo   = (const float*)d_in[12];
    const float* Wsk  = (const float*)d_in[13];
    const float* bsk  = (const float*)d_in[14];
    const float* gn   = (const float*)d_in[15];
    const float* bn   = (const float*)d_in[16];
    const float* ge   = (const float*)d_in[17];
    const float* be   = (const float*)d_in[18];
    float* out = (float*)d_out;

    k_node_ln<<<1024, 256>>>(node_feat, gn, bn);
    k_qkv<<<dim3(64, 3), 256>>>(Wqkv, bqkv);
    k_edge<<<1016, 256>>>(edge_feat, ge, be, Wea, bea, x_idx1, x_idx2, mask_valid);
    k_lsm<<<256, 256>>>();
    k_aggp<<<1024, 256>>>(Wev, bev);
    k_out<<<256, 256>>>(Wo, bo, Wsk, bsk, node_feat, out);
}